// round 12
// baseline (speedup 1.0000x reference)
#include <cuda_runtime.h>

// LSTM_584115552367: B=65536 independent LSTMs, D=H=17, T=50, SLB=30.
// R11: R10 constant-weight core, but each element's hidden units are SPLIT
// across a warp PAIR (role0: j=0..7, role1: j=8..16) with SMEM h-exchange per
// step. Doubles resident warps (occupancy was the R10 bottleneck: occ 21%,
// issue 43%, L1 6%, fma 38%). Role is warp-uniform -> constant path stays
// uniform (LDCU/LDC broadcast preserved).

#define BSZ   65536
#define TLEN  50
#define DDIM  17
#define SLBC  30
#define NP    9            // padded d-pairs (18/2)
#define TPB   128          // 4 warps: 2 element-groups x 2 roles
#define ELPC  64           // elements per CTA (32 per warp-pair group)
#define TOUT  (TLEN - SLBC)
#define XROW  18           // staging row stride (floats), 8B-aligned rows

// constant buffer layout (u64 units)
#define OFF_W    0                       // gate weights: ((j*9+p)*4+q)*2+h, 1224 u64
#define OFF_B    1224                    // biases: j*4 + {i,f,g,o}, 68 u64
#define OFF_LIN  1292                    // lin: ((ccp*9+p))*2+h, 162 u64
#define OFF_BLIN 1454                    // blin: cc, 18 u64
#define CBUF_N   1472

typedef unsigned long long u64;

__device__   u64 g_wbuf[CBUF_N];
__constant__ u64 cbuf[CBUF_N];

#define CW(j,p,q,h)  cbuf[OFF_W + (((j)*9 + (p))*4 + (q))*2 + (h)]
#define CB(j,g)      cbuf[OFF_B + (j)*4 + (g)]
#define CL(ccp,p,h)  cbuf[OFF_LIN + ((ccp)*9 + (p))*2 + (h)]
#define CBL(cc)      cbuf[OFF_BLIN + (cc)]

__device__ __forceinline__ u64 pack2(float lo, float hi) {
    u64 r; asm("mov.b64 %0, {%1, %2};" : "=l"(r) : "f"(lo), "f"(hi)); return r;
}
__device__ __forceinline__ void unpack2(u64 v, float &lo, float &hi) {
    asm("mov.b64 {%0, %1}, %2;" : "=f"(lo), "=f"(hi) : "l"(v));
}
__device__ __forceinline__ void fma2a(u64 &acc, u64 a, u64 b) {
    asm("fma.rn.f32x2 %0, %1, %2, %0;" : "+l"(acc) : "l"(a), "l"(b));
}
__device__ __forceinline__ float hadd2(u64 v) {
    float a, b; unpack2(v, a, b); return a + b;
}

__device__ __forceinline__ float ex2f(float x) {
    float r; asm("ex2.approx.f32 %0, %1;" : "=f"(r) : "f"(x)); return r;
}
__device__ __forceinline__ float rcpf(float x) {
    float r; asm("rcp.approx.f32 %0, %1;" : "=f"(r) : "f"(x)); return r;
}
// sigmoid(x) = 1 / (1 + 2^(-x*log2e)); safe at both extremes (rcp(inf)=0).
__device__ __forceinline__ float sigm(float x) {
    return rcpf(1.0f + ex2f(-1.4426950408889634f * x));
}
// tanh(x) = sign(x)*(1-e)/(1+e), e = 2^(-2|x|*log2e); e<=1, no inf/NaN.
__device__ __forceinline__ float tanhx(float x) {
    float ax = fabsf(x);
    float e  = ex2f(-2.8853900817779268f * ax);
    float r  = (1.0f - e) * rcpf(1.0f + e);
    return copysignf(r, x);
}

// ---- prep: pack masked weights/biases into g_wbuf (then memcpy'd to cbuf) ----
__global__ void prep_kernel(
    const float* __restrict__ Wih, const float* __restrict__ Whh,
    const float* __restrict__ bih, const float* __restrict__ bhh,
    const float* __restrict__ Wlin, const float* __restrict__ blin,
    const float* __restrict__ mih, const float* __restrict__ mhh)
{
    int tid = threadIdx.x;   // 128 threads, 1 block
    for (int idx = tid; idx < DDIM * NP * 4; idx += 128) {
        int j = idx / 36, r = idx % 36, p = r / 4, q = r % 4;
        const float* W = (q < 2) ? Wih : Whh;
        const float* M = (q < 2) ? mih : mhh;
        int gA = (q & 1) ? (34 + j) : j;
        int gB = (q & 1) ? (51 + j) : (17 + j);
        int d0 = 2 * p, d1 = 2 * p + 1;
        float a0 = W[gA * DDIM + d0] * M[gA * DDIM + d0];
        float a1 = (d1 < DDIM) ? W[gA * DDIM + d1] * M[gA * DDIM + d1] : 0.0f;
        float b0 = W[gB * DDIM + d0] * M[gB * DDIM + d0];
        float b1 = (d1 < DDIM) ? W[gB * DDIM + d1] * M[gB * DDIM + d1] : 0.0f;
        g_wbuf[OFF_W + idx * 2 + 0] = pack2(a0, a1);
        g_wbuf[OFF_W + idx * 2 + 1] = pack2(b0, b1);
    }
    for (int idx = tid; idx < NP * NP; idx += 128) {
        int ccp = idx / NP, p = idx % NP;
        int c0 = 2 * ccp, c1 = 2 * ccp + 1;
        int d0 = 2 * p, d1 = 2 * p + 1;
        float x0 = Wlin[c0 * DDIM + d0];
        float x1 = (d1 < DDIM) ? Wlin[c0 * DDIM + d1] : 0.0f;
        float y0 = (c1 < DDIM) ? Wlin[c1 * DDIM + d0] : 0.0f;
        float y1 = (c1 < DDIM && d1 < DDIM) ? Wlin[c1 * DDIM + d1] : 0.0f;
        g_wbuf[OFF_LIN + idx * 2 + 0] = pack2(x0, x1);
        g_wbuf[OFF_LIN + idx * 2 + 1] = pack2(y0, y1);
    }
    if (tid < DDIM) {
        int j = tid;
        g_wbuf[OFF_B + j * 4 + 0] = pack2(bih[j]      + bhh[j],      0.0f);
        g_wbuf[OFF_B + j * 4 + 1] = pack2(bih[17 + j] + bhh[17 + j], 0.0f);
        g_wbuf[OFF_B + j * 4 + 2] = pack2(bih[34 + j] + bhh[34 + j], 0.0f);
        g_wbuf[OFF_B + j * 4 + 3] = pack2(bih[51 + j] + bhh[51 + j], 0.0f);
    }
    if (tid < 2 * NP) {
        int cc = tid;
        g_wbuf[OFF_BLIN + cc] = (cc < DDIM) ? pack2(blin[cc], 0.0f) : 0ull;
    }
}

__global__ void __launch_bounds__(TPB, 5) lstm_kernel(
    const float* __restrict__ x,     // [B, T, D]
    float* __restrict__ out)         // [B, TOUT, D]
{
    __shared__ float sX[ELPC * XROW];   // x / out staging, one row per element
    __shared__ u64 sH[ELPC * 9];        // h exchange, 9 d-pairs per element

    const int tid  = threadIdx.x;
    const int warp = tid >> 5, lane = tid & 31;
    const int role = warp & 1;          // 0: j=0..7 & cc=0..8;  1: j=8..16 & cc=9..16
    const int grp  = warp >> 1;         // element group (32 elements each)
    const int el   = grp * 32 + lane;   // element within CTA
    const int jbase = role * 8;

    const long bi0 = (long)blockIdx.x * ELPC;
    float* __restrict__ myRow = sX + el * XROW;
    u64*   __restrict__ myH   = sH + el * 9;

    u64 xi[NP], h[NP], hn[5];
    float c[9];
#pragma unroll
    for (int p = 0; p < NP; p++) { xi[p] = 0ull; h[p] = 0ull; }
#pragma unroll
    for (int j = 0; j < 9; j++) c[j] = 0.0f;

#pragma unroll 1
    for (int t = 0; t < TLEN; t++) {
        __syncthreads();   // protect sH/sX from previous step's readers
        if (t < SLBC) {
            // Coalesced cooperative load: 64*17 floats for this CTA at step t.
#pragma unroll
            for (int k = 0; k < 9; k++) {
                int idx = tid + k * TPB;
                if (idx < ELPC * DDIM) {
                    int e2 = idx / DDIM, d = idx % DDIM;
                    sX[e2 * XROW + d] = x[(bi0 + e2) * (TLEN * DDIM) + t * DDIM + d];
                }
            }
            __syncthreads();
#pragma unroll
            for (int p = 0; p < 8; p++) xi[p] = ((const u64*)myRow)[p];
            xi[8] = pack2(myRow[16], 0.0f);
        }

        // ---- gates for this role's hidden units (4 j-pairs, 8 acc chains) ----
#pragma unroll
        for (int jj = 0; jj < 4; jj++) {
            const int j0 = jbase + 2 * jj, j1 = j0 + 1;
            u64 ai0 = CB(j0, 0), af0 = CB(j0, 1), ag0 = CB(j0, 2), ao0 = CB(j0, 3);
            u64 ai1 = CB(j1, 0), af1 = CB(j1, 1), ag1 = CB(j1, 2), ao1 = CB(j1, 3);
#pragma unroll
            for (int p = 0; p < NP; p++) {
                u64 xp = xi[p], hp = h[p];
                fma2a(ai0, xp, CW(j0, p, 0, 0)); fma2a(af0, xp, CW(j0, p, 0, 1));
                fma2a(ag0, xp, CW(j0, p, 1, 0)); fma2a(ao0, xp, CW(j0, p, 1, 1));
                fma2a(ai1, xp, CW(j1, p, 0, 0)); fma2a(af1, xp, CW(j1, p, 0, 1));
                fma2a(ag1, xp, CW(j1, p, 1, 0)); fma2a(ao1, xp, CW(j1, p, 1, 1));
                fma2a(ai0, hp, CW(j0, p, 2, 0)); fma2a(af0, hp, CW(j0, p, 2, 1));
                fma2a(ag0, hp, CW(j0, p, 3, 0)); fma2a(ao0, hp, CW(j0, p, 3, 1));
                fma2a(ai1, hp, CW(j1, p, 2, 0)); fma2a(af1, hp, CW(j1, p, 2, 1));
                fma2a(ag1, hp, CW(j1, p, 3, 0)); fma2a(ao1, hp, CW(j1, p, 3, 1));
            }
            float hn0, hn1;
            {
                float gi = hadd2(ai0), gf = hadd2(af0), gg = hadd2(ag0), go = hadd2(ao0);
                float cn = fmaf(sigm(gf), c[2 * jj], sigm(gi) * tanhx(gg));
                c[2 * jj] = cn; hn0 = sigm(go) * tanhx(cn);
            }
            {
                float gi = hadd2(ai1), gf = hadd2(af1), gg = hadd2(ag1), go = hadd2(ao1);
                float cn = fmaf(sigm(gf), c[2 * jj + 1], sigm(gi) * tanhx(gg));
                c[2 * jj + 1] = cn; hn1 = sigm(go) * tanhx(cn);
            }
            hn[jj] = pack2(hn0, hn1);
        }
        if (role) {   // tail j = 16 (warp-uniform branch)
            const int j = 16;
            u64 ai = CB(j, 0), af = CB(j, 1), ag = CB(j, 2), ao = CB(j, 3);
#pragma unroll
            for (int p = 0; p < NP; p++) {
                u64 xp = xi[p], hp = h[p];
                fma2a(ai, xp, CW(j, p, 0, 0)); fma2a(af, xp, CW(j, p, 0, 1));
                fma2a(ag, xp, CW(j, p, 1, 0)); fma2a(ao, xp, CW(j, p, 1, 1));
                fma2a(ai, hp, CW(j, p, 2, 0)); fma2a(af, hp, CW(j, p, 2, 1));
                fma2a(ag, hp, CW(j, p, 3, 0)); fma2a(ao, hp, CW(j, p, 3, 1));
            }
            float gi = hadd2(ai), gf = hadd2(af), gg = hadd2(ag), go = hadd2(ao);
            float cn = fmaf(sigm(gf), c[8], sigm(gi) * tanhx(gg));
            c[8] = cn;
            hn[4] = pack2(sigm(go) * tanhx(cn), 0.0f);
        }

        // ---- h exchange between the role pair ----
        if (!role) {
#pragma unroll
            for (int s = 0; s < 4; s++) myH[s] = hn[s];
        } else {
#pragma unroll
            for (int s = 0; s < 5; s++) myH[4 + s] = hn[s];
        }
        __syncthreads();
#pragma unroll
        for (int p = 0; p < NP; p++) h[p] = myH[p];

        if (t >= SLBC - 1) {
            // lin for this role's output channels: 4 ccp pairs + 1 single
            float o[9];
            const int pb = role * 5;    // role0: ccp 0..3 (cc0..7); role1: ccp 5..8 (cc10..17)
#pragma unroll
            for (int q = 0; q < 4; q++) {
                const int ccp = pb + q;
                u64 a0 = CBL(2 * ccp), a1 = CBL(2 * ccp + 1);
#pragma unroll
                for (int p = 0; p < NP; p++) {
                    fma2a(a0, h[p], CL(ccp, p, 0));
                    fma2a(a1, h[p], CL(ccp, p, 1));
                }
                o[2 * q] = hadd2(a0); o[2 * q + 1] = hadd2(a1);
            }
            {   // single channel: role0 -> cc8 (CL(4,*,0)); role1 -> cc9 (CL(4,*,1))
                u64 as = CBL(8 + role);
#pragma unroll
                for (int p = 0; p < NP; p++) fma2a(as, h[p], CL(4, p, role));
                o[8] = hadd2(as);
            }
            // stage o into element row (role-disjoint channels)
            if (!role) {
#pragma unroll
                for (int q = 0; q < 4; q++) { myRow[2 * q] = o[2 * q]; myRow[2 * q + 1] = o[2 * q + 1]; }
                myRow[8] = o[8];
            } else {
#pragma unroll
                for (int q = 0; q < 4; q++) {
                    myRow[10 + 2 * q] = o[2 * q];
                    if (11 + 2 * q < DDIM) myRow[11 + 2 * q] = o[2 * q + 1];
                }
                myRow[9] = o[8];
            }
            __syncthreads();
            if (t >= SLBC) {
                int tp = t - SLBC;
#pragma unroll
                for (int k = 0; k < 9; k++) {
                    int idx = tid + k * TPB;
                    if (idx < ELPC * DDIM) {
                        int e2 = idx / DDIM, d = idx % DDIM;
                        out[(bi0 + e2) * (TOUT * DDIM) + tp * DDIM + d] = sX[e2 * XROW + d];
                    }
                }
            }
            // feedback input for next step (full o from staging row)
#pragma unroll
            for (int p = 0; p < 8; p++) xi[p] = ((const u64*)myRow)[p];
            xi[8] = pack2(myRow[16], 0.0f);
        }
    }
}

extern "C" void kernel_launch(void* const* d_in, const int* in_sizes, int n_in,
                              void* d_out, int out_size) {
    const float* x    = (const float*)d_in[0];
    const float* Wih  = (const float*)d_in[1];
    const float* Whh  = (const float*)d_in[2];
    const float* bih  = (const float*)d_in[3];
    const float* bhh  = (const float*)d_in[4];
    const float* Wlin = (const float*)d_in[5];
    const float* blin = (const float*)d_in[6];
    const float* mih  = (const float*)d_in[7];
    const float* mhh  = (const float*)d_in[8];
    float* out = (float*)d_out;

    prep_kernel<<<1, 128>>>(Wih, Whh, bih, bhh, Wlin, blin, mih, mhh);
    void* src = nullptr;
    cudaGetSymbolAddress(&src, g_wbuf);
    cudaMemcpyToSymbolAsync(cbuf, src, CBUF_N * sizeof(u64), 0,
                            cudaMemcpyDeviceToDevice, 0);

    dim3 grid(BSZ / ELPC);   // 1024 CTAs of 128 threads (4096 warps)
    dim3 block(TPB);
    lstm_kernel<<<grid, block>>>(x, out);
}

// round 13
// speedup vs baseline: 4.0340x; 4.0340x over previous
#include <cuda_runtime.h>

// LSTM_584115552367: B=65536 independent LSTMs, D=H=17, T=50, SLB=30.
// R12: R6 core (best, 689.7us), weight traffic split across TWO ports:
//   ih gate weights  -> SMEM broadcast LDS.128 (l1tex port, R6 path)
//   hh gate weights, biases, lin -> __constant__ LDC.128 (constant port, R10 path)
// Each port carries ~half of R6's 612 loads/warp-step -> ports overlap.

#define BSZ   65536
#define TLEN  50
#define DDIM  17
#define SLBC  30
#define NP    9            // padded d-pairs (18/2)
#define TPB   64
#define TOUT  (TLEN - SLBC)
#define XROW  18           // staging row stride (floats), 8B-aligned rows

typedef unsigned long long u64;

// constant layout (ulonglong2 units):
//   [0..305]   hh weights: (j*9+p)*2+q, q=0:(i,f) pair, q=1:(g,o) pair
//   [306..339] biases: j*2 -> {(bi,0),(bf,0)}, j*2+1 -> {(bg,0),(bo,0)}
//   [340..420] lin: ccp*9+p -> {ch 2ccp d-pair, ch 2ccp+1 d-pair}
//   [421..429] blin: i -> {(blin[2i],0),(blin[2i+1],0)}
#define OFF_HH   0
#define OFF_B    306
#define OFF_LIN  340
#define OFF_BLIN 421
#define CBUF_N   430

__device__   ulonglong2 g_wbuf[CBUF_N];
__constant__ ulonglong2 cbuf[CBUF_N];

#define CWH(j,p,q)  cbuf[OFF_HH + ((j)*9 + (p))*2 + (q)]
#define CBIAS(j,q)  cbuf[OFF_B + (j)*2 + (q)]
#define CLIN(ccp,p) cbuf[OFF_LIN + (ccp)*9 + (p)]
#define CBLIN(i)    cbuf[OFF_BLIN + (i)]

__device__ __forceinline__ u64 pack2(float lo, float hi) {
    u64 r; asm("mov.b64 %0, {%1, %2};" : "=l"(r) : "f"(lo), "f"(hi)); return r;
}
__device__ __forceinline__ void unpack2(u64 v, float &lo, float &hi) {
    asm("mov.b64 {%0, %1}, %2;" : "=f"(lo), "=f"(hi) : "l"(v));
}
__device__ __forceinline__ void fma2a(u64 &acc, u64 a, u64 b) {
    asm("fma.rn.f32x2 %0, %1, %2, %0;" : "+l"(acc) : "l"(a), "l"(b));
}
__device__ __forceinline__ float hadd2(u64 v) {
    float a, b; unpack2(v, a, b); return a + b;
}

__device__ __forceinline__ float ex2f(float x) {
    float r; asm("ex2.approx.f32 %0, %1;" : "=f"(r) : "f"(x)); return r;
}
__device__ __forceinline__ float rcpf(float x) {
    float r; asm("rcp.approx.f32 %0, %1;" : "=f"(r) : "f"(x)); return r;
}
// sigmoid(x) = 1 / (1 + 2^(-x*log2e)); safe at both extremes (rcp(inf)=0).
__device__ __forceinline__ float sigm(float x) {
    return rcpf(1.0f + ex2f(-1.4426950408889634f * x));
}
// tanh(x) = sign(x)*(1-e)/(1+e), e = 2^(-2|x|*log2e); e<=1, no inf/NaN.
__device__ __forceinline__ float tanhx(float x) {
    float ax = fabsf(x);
    float e  = ex2f(-2.8853900817779268f * ax);
    float r  = (1.0f - e) * rcpf(1.0f + e);
    return copysignf(r, x);
}

// ---- prep: pack hh weights / biases / lin into g_wbuf (-> cbuf via memcpy) ----
__global__ void prep_kernel(
    const float* __restrict__ Whh,  const float* __restrict__ bih,
    const float* __restrict__ bhh,  const float* __restrict__ Wlin,
    const float* __restrict__ blin, const float* __restrict__ mhh)
{
    int tid = threadIdx.x;   // 128 threads, 1 block
    for (int idx = tid; idx < DDIM * NP * 2; idx += 128) {
        int j = idx / 18, r = idx % 18, p = r / 2, q = r % 2;
        int gA = q ? (34 + j) : j;
        int gB = q ? (51 + j) : (17 + j);
        int d0 = 2 * p, d1 = 2 * p + 1;
        float a0 = Whh[gA * DDIM + d0] * mhh[gA * DDIM + d0];
        float a1 = (d1 < DDIM) ? Whh[gA * DDIM + d1] * mhh[gA * DDIM + d1] : 0.0f;
        float b0 = Whh[gB * DDIM + d0] * mhh[gB * DDIM + d0];
        float b1 = (d1 < DDIM) ? Whh[gB * DDIM + d1] * mhh[gB * DDIM + d1] : 0.0f;
        ulonglong2 v; v.x = pack2(a0, a1); v.y = pack2(b0, b1);
        g_wbuf[OFF_HH + idx] = v;
    }
    for (int idx = tid; idx < NP * NP; idx += 128) {
        int ccp = idx / NP, p = idx % NP;
        int c0 = 2 * ccp, c1 = 2 * ccp + 1;
        int d0 = 2 * p, d1 = 2 * p + 1;
        float x0 = Wlin[c0 * DDIM + d0];
        float x1 = (d1 < DDIM) ? Wlin[c0 * DDIM + d1] : 0.0f;
        float y0 = (c1 < DDIM) ? Wlin[c1 * DDIM + d0] : 0.0f;
        float y1 = (c1 < DDIM && d1 < DDIM) ? Wlin[c1 * DDIM + d1] : 0.0f;
        ulonglong2 v; v.x = pack2(x0, x1); v.y = pack2(y0, y1);
        g_wbuf[OFF_LIN + idx] = v;
    }
    if (tid < DDIM) {
        int j = tid;
        ulonglong2 v0, v1;
        v0.x = pack2(bih[j]      + bhh[j],      0.0f);
        v0.y = pack2(bih[17 + j] + bhh[17 + j], 0.0f);
        v1.x = pack2(bih[34 + j] + bhh[34 + j], 0.0f);
        v1.y = pack2(bih[51 + j] + bhh[51 + j], 0.0f);
        g_wbuf[OFF_B + j * 2]     = v0;
        g_wbuf[OFF_B + j * 2 + 1] = v1;
    }
    if (tid < NP) {
        int i = tid;
        ulonglong2 v;
        v.x = pack2(blin[2 * i], 0.0f);
        v.y = (2 * i + 1 < DDIM) ? pack2(blin[2 * i + 1], 0.0f) : 0ull;
        g_wbuf[OFF_BLIN + i] = v;
    }
}

__global__ void __launch_bounds__(TPB, 7) lstm_kernel(
    const float* __restrict__ x,     // [B, T, D]
    const float* __restrict__ Wih,   // [4D, D]
    const float* __restrict__ mih,   // [4D, D]
    float* __restrict__ out)         // [B, TOUT, D]
{
    // ih gate weights only: (j*9+p)*2 + q, q=0:(i,f) d-pair, q=1:(g,o) d-pair
    __shared__ ulonglong2 sWih[DDIM * NP * 2];
    __shared__ float sStage[TPB * XROW];

    for (int idx = threadIdx.x; idx < DDIM * NP * 2; idx += TPB) {
        int j = idx / 18, r = idx % 18, p = r / 2, q = r % 2;
        int gA = q ? (34 + j) : j;
        int gB = q ? (51 + j) : (17 + j);
        int d0 = 2 * p, d1 = 2 * p + 1;
        float a0 = Wih[gA * DDIM + d0] * mih[gA * DDIM + d0];
        float a1 = (d1 < DDIM) ? Wih[gA * DDIM + d1] * mih[gA * DDIM + d1] : 0.0f;
        float b0 = Wih[gB * DDIM + d0] * mih[gB * DDIM + d0];
        float b1 = (d1 < DDIM) ? Wih[gB * DDIM + d1] * mih[gB * DDIM + d1] : 0.0f;
        ulonglong2 v; v.x = pack2(a0, a1); v.y = pack2(b0, b1);
        sWih[idx] = v;
    }
    __syncthreads();

    const int tid = threadIdx.x;
    const long bi0 = (long)blockIdx.x * TPB;
    const float* __restrict__ xg = x + bi0 * (TLEN * DDIM);
    float* __restrict__ og = out + bi0 * (TOUT * DDIM);
    const u64* __restrict__ sMyRow = (const u64*)(sStage + tid * XROW);

    u64 xi[NP], h[NP], hnew[NP];
    float c[DDIM];
#pragma unroll
    for (int p = 0; p < NP; p++) { xi[p] = 0ull; h[p] = 0ull; }
#pragma unroll
    for (int j = 0; j < DDIM; j++) c[j] = 0.0f;

#pragma unroll 1
    for (int t = 0; t < TLEN; t++) {
        if (t < SLBC) {
            __syncthreads();   // staging buffer free (prior readers done)
#pragma unroll
            for (int k = 0; k < DDIM; k++) {
                int idx = tid + k * TPB;             // coalesced
                int el = idx / DDIM, d = idx % DDIM;
                sStage[el * XROW + d] = xg[(long)el * (TLEN * DDIM) + t * DDIM + d];
            }
            __syncthreads();
#pragma unroll
            for (int p = 0; p < 8; p++) xi[p] = sMyRow[p];       // LDS.64
            {
                float lo, hi; unpack2(sMyRow[8], lo, hi);
                xi[8] = pack2(lo, 0.0f);
            }
        }

        // ---- LSTM cell: j-pairs; ih from SMEM (LDS), hh from constant (LDC) ----
#pragma unroll
        for (int jj = 0; jj < 8; jj++) {
            const int j0 = 2 * jj, j1 = 2 * jj + 1;
            ulonglong2 b00 = CBIAS(j0, 0), b01 = CBIAS(j0, 1);
            ulonglong2 b10 = CBIAS(j1, 0), b11 = CBIAS(j1, 1);
            u64 ai0 = b00.x, af0 = b00.y, ag0 = b01.x, ao0 = b01.y;
            u64 ai1 = b10.x, af1 = b10.y, ag1 = b11.x, ao1 = b11.y;
#pragma unroll
            for (int p = 0; p < NP; p++) {
                ulonglong2 wi00 = sWih[(j0 * NP + p) * 2 + 0];   // LDS port
                ulonglong2 wi01 = sWih[(j0 * NP + p) * 2 + 1];
                ulonglong2 wi10 = sWih[(j1 * NP + p) * 2 + 0];
                ulonglong2 wi11 = sWih[(j1 * NP + p) * 2 + 1];
                ulonglong2 wh00 = CWH(j0, p, 0);                 // LDC port
                ulonglong2 wh01 = CWH(j0, p, 1);
                ulonglong2 wh10 = CWH(j1, p, 0);
                ulonglong2 wh11 = CWH(j1, p, 1);
                u64 xp = xi[p], hp = h[p];
                fma2a(ai0, xp, wi00.x); fma2a(af0, xp, wi00.y);
                fma2a(ag0, xp, wi01.x); fma2a(ao0, xp, wi01.y);
                fma2a(ai1, xp, wi10.x); fma2a(af1, xp, wi10.y);
                fma2a(ag1, xp, wi11.x); fma2a(ao1, xp, wi11.y);
                fma2a(ai0, hp, wh00.x); fma2a(af0, hp, wh00.y);
                fma2a(ag0, hp, wh01.x); fma2a(ao0, hp, wh01.y);
                fma2a(ai1, hp, wh10.x); fma2a(af1, hp, wh10.y);
                fma2a(ag1, hp, wh11.x); fma2a(ao1, hp, wh11.y);
            }
            float hn0, hn1;
            {
                float gi = hadd2(ai0), gf = hadd2(af0), gg = hadd2(ag0), go = hadd2(ao0);
                float cn = fmaf(sigm(gf), c[j0], sigm(gi) * tanhx(gg));
                c[j0] = cn; hn0 = sigm(go) * tanhx(cn);
            }
            {
                float gi = hadd2(ai1), gf = hadd2(af1), gg = hadd2(ag1), go = hadd2(ao1);
                float cn = fmaf(sigm(gf), c[j1], sigm(gi) * tanhx(gg));
                c[j1] = cn; hn1 = sigm(go) * tanhx(cn);
            }
            hnew[jj] = pack2(hn0, hn1);
        }
        {   // tail j = 16
            const int j = 16;
            ulonglong2 b0 = CBIAS(j, 0), b1 = CBIAS(j, 1);
            u64 ai = b0.x, af = b0.y, ag = b1.x, ao = b1.y;
#pragma unroll
            for (int p = 0; p < NP; p++) {
                ulonglong2 wi0 = sWih[(j * NP + p) * 2 + 0];
                ulonglong2 wi1 = sWih[(j * NP + p) * 2 + 1];
                ulonglong2 wh0 = CWH(j, p, 0);
                ulonglong2 wh1 = CWH(j, p, 1);
                u64 xp = xi[p], hp = h[p];
                fma2a(ai, xp, wi0.x); fma2a(af, xp, wi0.y);
                fma2a(ag, xp, wi1.x); fma2a(ao, xp, wi1.y);
                fma2a(ai, hp, wh0.x); fma2a(af, hp, wh0.y);
                fma2a(ag, hp, wh1.x); fma2a(ao, hp, wh1.y);
            }
            float gi = hadd2(ai), gf = hadd2(af), gg = hadd2(ag), go = hadd2(ao);
            float cn = fmaf(sigm(gf), c[j], sigm(gi) * tanhx(gg));
            c[j] = cn;
            hnew[8] = pack2(sigm(go) * tanhx(cn), 0.0f);
        }
#pragma unroll
        for (int p = 0; p < NP; p++) h[p] = hnew[p];

        if (t >= SLBC - 1) {
            float o[2 * NP];
#pragma unroll
            for (int ccp = 0; ccp < NP; ccp++) {
                ulonglong2 bl = CBLIN(ccp);
                u64 a0 = bl.x, a1 = bl.y;
#pragma unroll
                for (int p = 0; p < NP; p++) {
                    ulonglong2 w = CLIN(ccp, p);
                    fma2a(a0, h[p], w.x);
                    fma2a(a1, h[p], w.y);
                }
                o[2 * ccp] = hadd2(a0); o[2 * ccp + 1] = hadd2(a1);
            }
            if (t >= SLBC) {
                int tp = t - SLBC;
                __syncthreads();   // buffer free (prior step's STG readers done)
                u64* myRowW = (u64*)(sStage + tid * XROW);
#pragma unroll
                for (int p = 0; p < NP; p++)
                    myRowW[p] = pack2(o[2 * p], (2 * p + 1 < DDIM) ? o[2 * p + 1] : 0.0f);
                __syncthreads();
#pragma unroll
                for (int k = 0; k < DDIM; k++) {
                    int idx = tid + k * TPB;
                    int el = idx / DDIM, d = idx % DDIM;
                    og[(long)el * (TOUT * DDIM) + tp * DDIM + d] = sStage[el * XROW + d];
                }
            }
            // Feedback input for next step.
#pragma unroll
            for (int p = 0; p < 8; p++) xi[p] = pack2(o[2 * p], o[2 * p + 1]);
            xi[8] = pack2(o[16], 0.0f);
        }
    }
}

extern "C" void kernel_launch(void* const* d_in, const int* in_sizes, int n_in,
                              void* d_out, int out_size) {
    const float* x    = (const float*)d_in[0];
    const float* Wih  = (const float*)d_in[1];
    const float* Whh  = (const float*)d_in[2];
    const float* bih  = (const float*)d_in[3];
    const float* bhh  = (const float*)d_in[4];
    const float* Wlin = (const float*)d_in[5];
    const float* blin = (const float*)d_in[6];
    const float* mih  = (const float*)d_in[7];
    const float* mhh  = (const float*)d_in[8];
    float* out = (float*)d_out;

    prep_kernel<<<1, 128>>>(Whh, bih, bhh, Wlin, blin, mhh);
    void* src = nullptr;
    cudaGetSymbolAddress(&src, g_wbuf);
    cudaMemcpyToSymbolAsync(cbuf, src, CBUF_N * sizeof(ulonglong2), 0,
                            cudaMemcpyDeviceToDevice, 0);

    dim3 grid(BSZ / TPB);   // 1024 CTAs of 64 threads
    dim3 block(TPB);
    lstm_kernel<<<grid, block>>>(x, Wih, mih, out);
}

// round 15
// speedup vs baseline: 4.1910x; 1.0389x over previous
#include <cuda_runtime.h>

// LSTM_584115552367: B=65536 independent LSTMs, D=H=17, T=50, SLB=30.
// R13 (resubmit after infra failure): R12 port-split core (best, 601.2us) +
//  - biases folded into pad lanes (xi[8].hi = 1.0 carries gate bias via ih pad
//    weight; h[8].hi = 1.0 carries blin via lin pad weight) -> deletes 34
//    bias LDC.128/step + 9 blin LDC/out-step, balances LDC port to 306 = LDS.
//  - p==0 accumulator init via mul2 (no load/mov at loop head).
//  - tanh(x) = 2*sigm(2x)-1 (5 ops vs 8; saturates correctly at +-inf).

#define BSZ   65536
#define TLEN  50
#define DDIM  17
#define SLBC  30
#define NP    9            // padded d-pairs (18/2)
#define TPB   64
#define TOUT  (TLEN - SLBC)
#define XROW  18           // staging row stride (floats), 8B-aligned rows

typedef unsigned long long u64;

// constant layout (ulonglong2 units):
//   [0..305]   hh weights: (j*9+p)*2+q, q=0:(i,f) pair, q=1:(g,o) pair; pads 0
//   [306..386] lin: ccp*9+p -> {ch c0 d-pair, ch c1 d-pair}; p=8 lane1 = blin
#define OFF_HH   0
#define OFF_LIN  306
#define CBUF_N   387

__device__   ulonglong2 g_wbuf[CBUF_N];
__constant__ ulonglong2 cbuf[CBUF_N];

#define CWH(j,p,q)  cbuf[OFF_HH + ((j)*9 + (p))*2 + (q)]
#define CLIN(ccp,p) cbuf[OFF_LIN + (ccp)*9 + (p)]

__device__ __forceinline__ u64 pack2(float lo, float hi) {
    u64 r; asm("mov.b64 %0, {%1, %2};" : "=l"(r) : "f"(lo), "f"(hi)); return r;
}
__device__ __forceinline__ void unpack2(u64 v, float &lo, float &hi) {
    asm("mov.b64 {%0, %1}, %2;" : "=f"(lo), "=f"(hi) : "l"(v));
}
__device__ __forceinline__ void fma2a(u64 &acc, u64 a, u64 b) {
    asm("fma.rn.f32x2 %0, %1, %2, %0;" : "+l"(acc) : "l"(a), "l"(b));
}
__device__ __forceinline__ u64 mul2(u64 a, u64 b) {
    u64 r; asm("mul.rn.f32x2 %0, %1, %2;" : "=l"(r) : "l"(a), "l"(b)); return r;
}
__device__ __forceinline__ float hadd2(u64 v) {
    float a, b; unpack2(v, a, b); return a + b;
}

__device__ __forceinline__ float ex2f(float x) {
    float r; asm("ex2.approx.f32 %0, %1;" : "=f"(r) : "f"(x)); return r;
}
__device__ __forceinline__ float rcpf(float x) {
    float r; asm("rcp.approx.f32 %0, %1;" : "=f"(r) : "f"(x)); return r;
}
// sigmoid(x) = 1 / (1 + 2^(-x*log2e)); safe at both extremes (rcp(inf)=0).
__device__ __forceinline__ float sigm(float x) {
    return rcpf(1.0f + ex2f(-1.4426950408889634f * x));
}
// tanh(x) = 2*sigmoid(2x) - 1; endpoints: rcp(inf)=0 -> -1, rcp(1)=1 -> +1.
__device__ __forceinline__ float tanhx(float x) {
    float e = ex2f(-2.8853900817779268f * x);   // 2^(-2x*log2e)
    return fmaf(2.0f, rcpf(1.0f + e), -1.0f);
}

// ---- prep: pack hh weights / lin(+blin) into g_wbuf (-> cbuf via memcpy) ----
__global__ void prep_kernel(
    const float* __restrict__ Whh,  const float* __restrict__ Wlin,
    const float* __restrict__ blin, const float* __restrict__ mhh)
{
    int tid = threadIdx.x;   // 128 threads, 1 block
    for (int idx = tid; idx < DDIM * NP * 2; idx += 128) {
        int j = idx / 18, r = idx % 18, p = r / 2, q = r % 2;
        int gA = q ? (34 + j) : j;
        int gB = q ? (51 + j) : (17 + j);
        int d0 = 2 * p, d1 = 2 * p + 1;
        float a0 = Whh[gA * DDIM + d0] * mhh[gA * DDIM + d0];
        float a1 = (d1 < DDIM) ? Whh[gA * DDIM + d1] * mhh[gA * DDIM + d1] : 0.0f;
        float b0 = Whh[gB * DDIM + d0] * mhh[gB * DDIM + d0];
        float b1 = (d1 < DDIM) ? Whh[gB * DDIM + d1] * mhh[gB * DDIM + d1] : 0.0f;
        ulonglong2 v; v.x = pack2(a0, a1); v.y = pack2(b0, b1);
        g_wbuf[OFF_HH + idx] = v;
    }
    for (int idx = tid; idx < NP * NP; idx += 128) {
        int ccp = idx / NP, p = idx % NP;
        int c0 = 2 * ccp, c1 = 2 * ccp + 1;
        int d0 = 2 * p, d1 = 2 * p + 1;
        float x0 = Wlin[c0 * DDIM + d0];
        float x1 = (d1 < DDIM) ? Wlin[c0 * DDIM + d1] : blin[c0];   // pad lane = blin
        float y0 = (c1 < DDIM) ? Wlin[c1 * DDIM + d0] : 0.0f;
        float y1 = (c1 < DDIM) ? ((d1 < DDIM) ? Wlin[c1 * DDIM + d1] : blin[c1]) : 0.0f;
        ulonglong2 v; v.x = pack2(x0, x1); v.y = pack2(y0, y1);
        g_wbuf[OFF_LIN + idx] = v;
    }
}

__global__ void __launch_bounds__(TPB, 7) lstm_kernel(
    const float* __restrict__ x,     // [B, T, D]
    const float* __restrict__ Wih,   // [4D, D]
    const float* __restrict__ mih,   // [4D, D]
    const float* __restrict__ bih,   // [4D]
    const float* __restrict__ bhh,   // [4D]
    float* __restrict__ out)         // [B, TOUT, D]
{
    // ih gate weights: (j*9+p)*2 + q, q=0:(i,f) d-pair, q=1:(g,o) d-pair.
    // Pad lane (p=8, d=17) carries the combined gate bias (bih+bhh).
    __shared__ ulonglong2 sWih[DDIM * NP * 2];
    __shared__ float sStage[TPB * XROW];

    for (int idx = threadIdx.x; idx < DDIM * NP * 2; idx += TPB) {
        int j = idx / 18, r = idx % 18, p = r / 2, q = r % 2;
        int gA = q ? (34 + j) : j;
        int gB = q ? (51 + j) : (17 + j);
        int d0 = 2 * p, d1 = 2 * p + 1;
        float a0 = Wih[gA * DDIM + d0] * mih[gA * DDIM + d0];
        float a1 = (d1 < DDIM) ? Wih[gA * DDIM + d1] * mih[gA * DDIM + d1]
                               : (bih[gA] + bhh[gA]);
        float b0 = Wih[gB * DDIM + d0] * mih[gB * DDIM + d0];
        float b1 = (d1 < DDIM) ? Wih[gB * DDIM + d1] * mih[gB * DDIM + d1]
                               : (bih[gB] + bhh[gB]);
        ulonglong2 v; v.x = pack2(a0, a1); v.y = pack2(b0, b1);
        sWih[idx] = v;
    }
    __syncthreads();

    const int tid = threadIdx.x;
    const long bi0 = (long)blockIdx.x * TPB;
    const float* __restrict__ xg = x + bi0 * (TLEN * DDIM);
    float* __restrict__ og = out + bi0 * (TOUT * DDIM);
    const u64* __restrict__ sMyRow = (const u64*)(sStage + tid * XROW);

    u64 xi[NP], h[NP], hnew[NP];
    float c[DDIM];
#pragma unroll
    for (int p = 0; p < NP; p++) { xi[p] = 0ull; h[p] = 0ull; }
    h[8] = pack2(0.0f, 1.0f);    // hi lane = 1.0 carries blin through lin pad
#pragma unroll
    for (int j = 0; j < DDIM; j++) c[j] = 0.0f;

#pragma unroll 1
    for (int t = 0; t < TLEN; t++) {
        if (t < SLBC) {
            __syncthreads();   // staging buffer free (prior readers done)
#pragma unroll
            for (int k = 0; k < DDIM; k++) {
                int idx = tid + k * TPB;             // coalesced
                int el = idx / DDIM, d = idx % DDIM;
                sStage[el * XROW + d] = xg[(long)el * (TLEN * DDIM) + t * DDIM + d];
            }
            __syncthreads();
#pragma unroll
            for (int p = 0; p < 8; p++) xi[p] = sMyRow[p];       // LDS.64
            {
                float lo, hi; unpack2(sMyRow[8], lo, hi);
                xi[8] = pack2(lo, 1.0f);   // hi lane = 1.0 carries gate bias
            }
        }

        // ---- LSTM cell: j-pairs; ih from SMEM (LDS), hh from constant (LDC) ----
#pragma unroll
        for (int jj = 0; jj < 8; jj++) {
            const int j0 = 2 * jj, j1 = 2 * jj + 1;
            u64 ai0, af0, ag0, ao0, ai1, af1, ag1, ao1;
#pragma unroll
            for (int p = 0; p < NP; p++) {
                ulonglong2 wi00 = sWih[(j0 * NP + p) * 2 + 0];   // LDS port
                ulonglong2 wi01 = sWih[(j0 * NP + p) * 2 + 1];
                ulonglong2 wi10 = sWih[(j1 * NP + p) * 2 + 0];
                ulonglong2 wi11 = sWih[(j1 * NP + p) * 2 + 1];
                ulonglong2 wh00 = CWH(j0, p, 0);                 // LDC port
                ulonglong2 wh01 = CWH(j0, p, 1);
                ulonglong2 wh10 = CWH(j1, p, 0);
                ulonglong2 wh11 = CWH(j1, p, 1);
                u64 xp = xi[p], hp = h[p];
                if (p == 0) {
                    ai0 = mul2(xp, wi00.x); af0 = mul2(xp, wi00.y);
                    ag0 = mul2(xp, wi01.x); ao0 = mul2(xp, wi01.y);
                    ai1 = mul2(xp, wi10.x); af1 = mul2(xp, wi10.y);
                    ag1 = mul2(xp, wi11.x); ao1 = mul2(xp, wi11.y);
                } else {
                    fma2a(ai0, xp, wi00.x); fma2a(af0, xp, wi00.y);
                    fma2a(ag0, xp, wi01.x); fma2a(ao0, xp, wi01.y);
                    fma2a(ai1, xp, wi10.x); fma2a(af1, xp, wi10.y);
                    fma2a(ag1, xp, wi11.x); fma2a(ao1, xp, wi11.y);
                }
                fma2a(ai0, hp, wh00.x); fma2a(af0, hp, wh00.y);
                fma2a(ag0, hp, wh01.x); fma2a(ao0, hp, wh01.y);
                fma2a(ai1, hp, wh10.x); fma2a(af1, hp, wh10.y);
                fma2a(ag1, hp, wh11.x); fma2a(ao1, hp, wh11.y);
            }
            float hn0, hn1;
            {
                float gi = hadd2(ai0), gf = hadd2(af0), gg = hadd2(ag0), go = hadd2(ao0);
                float cn = fmaf(sigm(gf), c[j0], sigm(gi) * tanhx(gg));
                c[j0] = cn; hn0 = sigm(go) * tanhx(cn);
            }
            {
                float gi = hadd2(ai1), gf = hadd2(af1), gg = hadd2(ag1), go = hadd2(ao1);
                float cn = fmaf(sigm(gf), c[j1], sigm(gi) * tanhx(gg));
                c[j1] = cn; hn1 = sigm(go) * tanhx(cn);
            }
            hnew[jj] = pack2(hn0, hn1);
        }
        {   // tail j = 16
            const int j = 16;
            u64 ai, af, ag, ao;
#pragma unroll
            for (int p = 0; p < NP; p++) {
                ulonglong2 wi0 = sWih[(j * NP + p) * 2 + 0];
                ulonglong2 wi1 = sWih[(j * NP + p) * 2 + 1];
                ulonglong2 wh0 = CWH(j, p, 0);
                ulonglong2 wh1 = CWH(j, p, 1);
                u64 xp = xi[p], hp = h[p];
                if (p == 0) {
                    ai = mul2(xp, wi0.x); af = mul2(xp, wi0.y);
                    ag = mul2(xp, wi1.x); ao = mul2(xp, wi1.y);
                } else {
                    fma2a(ai, xp, wi0.x); fma2a(af, xp, wi0.y);
                    fma2a(ag, xp, wi1.x); fma2a(ao, xp, wi1.y);
                }
                fma2a(ai, hp, wh0.x); fma2a(af, hp, wh0.y);
                fma2a(ag, hp, wh1.x); fma2a(ao, hp, wh1.y);
            }
            float gi = hadd2(ai), gf = hadd2(af), gg = hadd2(ag), go = hadd2(ao);
            float cn = fmaf(sigm(gf), c[j], sigm(gi) * tanhx(gg));
            c[j] = cn;
            hnew[8] = pack2(sigm(go) * tanhx(cn), 1.0f);   // hi lane = 1.0 (blin)
        }
#pragma unroll
        for (int p = 0; p < NP; p++) h[p] = hnew[p];

        if (t >= SLBC - 1) {
            float o[2 * NP];
#pragma unroll
            for (int ccp = 0; ccp < NP; ccp++) {
                u64 a0, a1;
#pragma unroll
                for (int p = 0; p < NP; p++) {
                    ulonglong2 w = CLIN(ccp, p);
                    if (p == 0) { a0 = mul2(h[0], w.x); a1 = mul2(h[0], w.y); }
                    else        { fma2a(a0, h[p], w.x); fma2a(a1, h[p], w.y); }
                }
                o[2 * ccp] = hadd2(a0); o[2 * ccp + 1] = hadd2(a1);
            }
            if (t >= SLBC) {
                int tp = t - SLBC;
                __syncthreads();   // buffer free (prior step's STG readers done)
                u64* myRowW = (u64*)(sStage + tid * XROW);
#pragma unroll
                for (int p = 0; p < NP; p++)
                    myRowW[p] = pack2(o[2 * p], (2 * p + 1 < DDIM) ? o[2 * p + 1] : 0.0f);
                __syncthreads();
#pragma unroll
                for (int k = 0; k < DDIM; k++) {
                    int idx = tid + k * TPB;
                    int el = idx / DDIM, d = idx % DDIM;
                    og[(long)el * (TOUT * DDIM) + tp * DDIM + d] = sStage[el * XROW + d];
                }
            }
            // Feedback input for next step (hi lane of pad pair = 1.0 for bias).
#pragma unroll
            for (int p = 0; p < 8; p++) xi[p] = pack2(o[2 * p], o[2 * p + 1]);
            xi[8] = pack2(o[16], 1.0f);
        }
    }
}

extern "C" void kernel_launch(void* const* d_in, const int* in_sizes, int n_in,
                              void* d_out, int out_size) {
    const float* x    = (const float*)d_in[0];
    const float* Wih  = (const float*)d_in[1];
    const float* Whh  = (const float*)d_in[2];
    const float* bih  = (const float*)d_in[3];
    const float* bhh  = (const float*)d_in[4];
    const float* Wlin = (const float*)d_in[5];
    const float* blin = (const float*)d_in[6];
    const float* mih  = (const float*)d_in[7];
    const float* mhh  = (const float*)d_in[8];
    float* out = (float*)d_out;

    prep_kernel<<<1, 128>>>(Whh, Wlin, blin, mhh);
    void* src = nullptr;
    cudaGetSymbolAddress(&src, g_wbuf);
    cudaMemcpyToSymbolAsync(cbuf, src, CBUF_N * sizeof(ulonglong2), 0,
                            cudaMemcpyDeviceToDevice, 0);

    dim3 grid(BSZ / TPB);   // 1024 CTAs of 64 threads
    dim3 block(TPB);
    lstm_kernel<<<grid, block>>>(x, Wih, mih, bih, bhh, out);
}

// round 16
// speedup vs baseline: 4.6099x; 1.0999x over previous
#include <cuda_runtime.h>

// LSTM_584115552367: B=65536 independent LSTMs, D=H=17, T=50, SLB=30.
// R14: R13 core (best, 578.7us) + feedback-phase algebraic collapse:
//   for t>=SLB, xi = h_prev@Wlin^T + blin, carry = h_prev, so
//   gates = h_prev @ (Wlin^T Wih^T + Whh^T) + (blin@Wih^T + b) = h_prev@Wcomb.
//   One matvec instead of two: -612 fma2, -153 loads per feedback step, and
//   the lin->feedback->gates serial dependency disappears (lin is now a leaf).
//   Wcomb (i,f) half -> SMEM, (g,o) half -> constant (port balance kept);
//   composite bias rides the pad lane via h[8].hi = 1.0.

#define BSZ   65536
#define TLEN  50
#define DDIM  17
#define SLBC  30
#define NP    9            // padded d-pairs (18/2)
#define TPB   64
#define TOUT  (TLEN - SLBC)
#define XROW  18           // staging row stride (floats), 8B-aligned rows

typedef unsigned long long u64;

// constant layout (ulonglong2 units):
//   [0..305]   hh weights: (j*9+p)*2+q, q=0:(i,f) pair, q=1:(g,o) pair; pads 0
//   [306..386] lin: ccp*9+p -> {ch c0 d-pair, ch c1 d-pair}; p=8 lane1 = blin
//   [387..539] Wcomb (g,o) pairs: j*9+p; pad lane (p=8,hi) = bias_comb
#define OFF_HH   0
#define OFF_LIN  306
#define OFF_CGO  387
#define CBUF_N   540

__device__   ulonglong2 g_wbuf[CBUF_N];
__device__   ulonglong2 g_wcomb_if[DDIM * NP];   // Wcomb (i,f) pairs -> SMEM
__constant__ ulonglong2 cbuf[CBUF_N];

#define CWH(j,p,q)  cbuf[OFF_HH + ((j)*9 + (p))*2 + (q)]
#define CLIN(ccp,p) cbuf[OFF_LIN + (ccp)*9 + (p)]
#define CCGO(j,p)   cbuf[OFF_CGO + (j)*9 + (p)]

__device__ __forceinline__ u64 pack2(float lo, float hi) {
    u64 r; asm("mov.b64 %0, {%1, %2};" : "=l"(r) : "f"(lo), "f"(hi)); return r;
}
__device__ __forceinline__ void unpack2(u64 v, float &lo, float &hi) {
    asm("mov.b64 {%0, %1}, %2;" : "=f"(lo), "=f"(hi) : "l"(v));
}
__device__ __forceinline__ void fma2a(u64 &acc, u64 a, u64 b) {
    asm("fma.rn.f32x2 %0, %1, %2, %0;" : "+l"(acc) : "l"(a), "l"(b));
}
__device__ __forceinline__ u64 mul2(u64 a, u64 b) {
    u64 r; asm("mul.rn.f32x2 %0, %1, %2;" : "=l"(r) : "l"(a), "l"(b)); return r;
}
__device__ __forceinline__ float hadd2(u64 v) {
    float a, b; unpack2(v, a, b); return a + b;
}

__device__ __forceinline__ float ex2f(float x) {
    float r; asm("ex2.approx.f32 %0, %1;" : "=f"(r) : "f"(x)); return r;
}
__device__ __forceinline__ float rcpf(float x) {
    float r; asm("rcp.approx.f32 %0, %1;" : "=f"(r) : "f"(x)); return r;
}
// sigmoid(x) = 1 / (1 + 2^(-x*log2e)); safe at both extremes (rcp(inf)=0).
__device__ __forceinline__ float sigm(float x) {
    return rcpf(1.0f + ex2f(-1.4426950408889634f * x));
}
// tanh(x) = 2*sigmoid(2x) - 1; endpoints: rcp(inf)=0 -> -1, rcp(1)=1 -> +1.
__device__ __forceinline__ float tanhx(float x) {
    float e = ex2f(-2.8853900817779268f * x);   // 2^(-2x*log2e)
    return fmaf(2.0f, rcpf(1.0f + e), -1.0f);
}

// ---- prep: pack hh / lin(+blin) / Wcomb into device buffers ----
__global__ void prep_kernel(
    const float* __restrict__ Wih,  const float* __restrict__ Whh,
    const float* __restrict__ bih,  const float* __restrict__ bhh,
    const float* __restrict__ Wlin, const float* __restrict__ blin,
    const float* __restrict__ mih,  const float* __restrict__ mhh)
{
    int tid = threadIdx.x;   // 128 threads, 1 block
    // hh gate weights (unchanged layout)
    for (int idx = tid; idx < DDIM * NP * 2; idx += 128) {
        int j = idx / 18, r = idx % 18, p = r / 2, q = r % 2;
        int gA = q ? (34 + j) : j;
        int gB = q ? (51 + j) : (17 + j);
        int d0 = 2 * p, d1 = 2 * p + 1;
        float a0 = Whh[gA * DDIM + d0] * mhh[gA * DDIM + d0];
        float a1 = (d1 < DDIM) ? Whh[gA * DDIM + d1] * mhh[gA * DDIM + d1] : 0.0f;
        float b0 = Whh[gB * DDIM + d0] * mhh[gB * DDIM + d0];
        float b1 = (d1 < DDIM) ? Whh[gB * DDIM + d1] * mhh[gB * DDIM + d1] : 0.0f;
        ulonglong2 v; v.x = pack2(a0, a1); v.y = pack2(b0, b1);
        g_wbuf[OFF_HH + idx] = v;
    }
    // lin (+blin in pad lane)
    for (int idx = tid; idx < NP * NP; idx += 128) {
        int ccp = idx / NP, p = idx % NP;
        int c0 = 2 * ccp, c1 = 2 * ccp + 1;
        int d0 = 2 * p, d1 = 2 * p + 1;
        float x0 = Wlin[c0 * DDIM + d0];
        float x1 = (d1 < DDIM) ? Wlin[c0 * DDIM + d1] : blin[c0];
        float y0 = (c1 < DDIM) ? Wlin[c1 * DDIM + d0] : 0.0f;
        float y1 = (c1 < DDIM) ? ((d1 < DDIM) ? Wlin[c1 * DDIM + d1] : blin[c1]) : 0.0f;
        ulonglong2 v; v.x = pack2(x0, x1); v.y = pack2(y0, y1);
        g_wbuf[OFF_LIN + idx] = v;
    }
    // Wcomb[k,g] = sum_m Wlin[m*17+k] * Wih[g*17+m]*mih[g*17+m] + Whh[g*17+k]*mhh[g*17+k]
    // bias_comb[g] = sum_m blin[m] * Wih[g*17+m]*mih[g*17+m] + bih[g]+bhh[g]
    for (int idx = tid; idx < DDIM * NP * 2; idx += 128) {
        int j = idx / 18, r = idx % 18, p = r / 2, q = r % 2;
        int gA = q ? (34 + j) : j;        // q=0: (i,f); q=1: (g,o)
        int gB = q ? (51 + j) : (17 + j);
        int d0 = 2 * p, d1 = 2 * p + 1;
        float vals[4];
        int gs[2] = {gA, gB};
#pragma unroll
        for (int s = 0; s < 2; s++) {
            int g = gs[s];
            // k = d0
            float acc0 = Whh[g * DDIM + d0] * mhh[g * DDIM + d0];
            for (int m = 0; m < DDIM; m++)
                acc0 += Wlin[m * DDIM + d0] * Wih[g * DDIM + m] * mih[g * DDIM + m];
            float acc1;
            if (d1 < DDIM) {
                acc1 = Whh[g * DDIM + d1] * mhh[g * DDIM + d1];
                for (int m = 0; m < DDIM; m++)
                    acc1 += Wlin[m * DDIM + d1] * Wih[g * DDIM + m] * mih[g * DDIM + m];
            } else {
                acc1 = bih[g] + bhh[g];
                for (int m = 0; m < DDIM; m++)
                    acc1 += blin[m] * Wih[g * DDIM + m] * mih[g * DDIM + m];
            }
            vals[2 * s]     = acc0;
            vals[2 * s + 1] = acc1;
        }
        ulonglong2 v; v.x = pack2(vals[0], vals[1]); v.y = pack2(vals[2], vals[3]);
        if (q == 0) g_wcomb_if[j * NP + p] = v;           // (i,f) -> SMEM side
        else        g_wbuf[OFF_CGO + j * NP + p] = v;     // (g,o) -> constant side
    }
}

__global__ void __launch_bounds__(TPB, 7) lstm_kernel(
    const float* __restrict__ x,     // [B, T, D]
    const float* __restrict__ Wih,   // [4D, D]
    const float* __restrict__ mih,   // [4D, D]
    const float* __restrict__ bih,   // [4D]
    const float* __restrict__ bhh,   // [4D]
    float* __restrict__ out)         // [B, TOUT, D]
{
    // ih gate weights: (j*9+p)*2 + q; pad lane (p=8,d17) = combined gate bias.
    __shared__ ulonglong2 sWih[DDIM * NP * 2];
    __shared__ ulonglong2 sWcIF[DDIM * NP];      // Wcomb (i,f) pairs
    __shared__ float sStage[TPB * XROW];

    for (int idx = threadIdx.x; idx < DDIM * NP * 2; idx += TPB) {
        int j = idx / 18, r = idx % 18, p = r / 2, q = r % 2;
        int gA = q ? (34 + j) : j;
        int gB = q ? (51 + j) : (17 + j);
        int d0 = 2 * p, d1 = 2 * p + 1;
        float a0 = Wih[gA * DDIM + d0] * mih[gA * DDIM + d0];
        float a1 = (d1 < DDIM) ? Wih[gA * DDIM + d1] * mih[gA * DDIM + d1]
                               : (bih[gA] + bhh[gA]);
        float b0 = Wih[gB * DDIM + d0] * mih[gB * DDIM + d0];
        float b1 = (d1 < DDIM) ? Wih[gB * DDIM + d1] * mih[gB * DDIM + d1]
                               : (bih[gB] + bhh[gB]);
        ulonglong2 v; v.x = pack2(a0, a1); v.y = pack2(b0, b1);
        sWih[idx] = v;
    }
    for (int idx = threadIdx.x; idx < DDIM * NP; idx += TPB)
        sWcIF[idx] = g_wcomb_if[idx];
    __syncthreads();

    const int tid = threadIdx.x;
    const long bi0 = (long)blockIdx.x * TPB;
    const float* __restrict__ xg = x + bi0 * (TLEN * DDIM);
    float* __restrict__ og = out + bi0 * (TOUT * DDIM);
    const u64* __restrict__ sMyRow = (const u64*)(sStage + tid * XROW);

    u64 xi[NP], h[NP], hnew[NP];
    float c[DDIM];
#pragma unroll
    for (int p = 0; p < NP; p++) { xi[p] = 0ull; h[p] = 0ull; }
    h[8] = pack2(0.0f, 1.0f);    // hi lane = 1.0 carries blin / bias_comb pads
#pragma unroll
    for (int j = 0; j < DDIM; j++) c[j] = 0.0f;

#pragma unroll 1
    for (int t = 0; t < TLEN; t++) {
        if (t < SLBC) {
            // ---- teacher phase: stage x, gates = xi@ih(LDS) + h@hh(LDC) ----
            __syncthreads();
#pragma unroll
            for (int k = 0; k < DDIM; k++) {
                int idx = tid + k * TPB;             // coalesced
                int el = idx / DDIM, d = idx % DDIM;
                sStage[el * XROW + d] = xg[(long)el * (TLEN * DDIM) + t * DDIM + d];
            }
            __syncthreads();
#pragma unroll
            for (int p = 0; p < 8; p++) xi[p] = sMyRow[p];       // LDS.64
            {
                float lo, hi; unpack2(sMyRow[8], lo, hi);
                xi[8] = pack2(lo, 1.0f);   // hi lane = 1.0 carries gate bias
            }

#pragma unroll
            for (int jj = 0; jj < 8; jj++) {
                const int j0 = 2 * jj, j1 = 2 * jj + 1;
                u64 ai0, af0, ag0, ao0, ai1, af1, ag1, ao1;
#pragma unroll
                for (int p = 0; p < NP; p++) {
                    ulonglong2 wi00 = sWih[(j0 * NP + p) * 2 + 0];
                    ulonglong2 wi01 = sWih[(j0 * NP + p) * 2 + 1];
                    ulonglong2 wi10 = sWih[(j1 * NP + p) * 2 + 0];
                    ulonglong2 wi11 = sWih[(j1 * NP + p) * 2 + 1];
                    ulonglong2 wh00 = CWH(j0, p, 0);
                    ulonglong2 wh01 = CWH(j0, p, 1);
                    ulonglong2 wh10 = CWH(j1, p, 0);
                    ulonglong2 wh11 = CWH(j1, p, 1);
                    u64 xp = xi[p], hp = h[p];
                    if (p == 0) {
                        ai0 = mul2(xp, wi00.x); af0 = mul2(xp, wi00.y);
                        ag0 = mul2(xp, wi01.x); ao0 = mul2(xp, wi01.y);
                        ai1 = mul2(xp, wi10.x); af1 = mul2(xp, wi10.y);
                        ag1 = mul2(xp, wi11.x); ao1 = mul2(xp, wi11.y);
                    } else {
                        fma2a(ai0, xp, wi00.x); fma2a(af0, xp, wi00.y);
                        fma2a(ag0, xp, wi01.x); fma2a(ao0, xp, wi01.y);
                        fma2a(ai1, xp, wi10.x); fma2a(af1, xp, wi10.y);
                        fma2a(ag1, xp, wi11.x); fma2a(ao1, xp, wi11.y);
                    }
                    fma2a(ai0, hp, wh00.x); fma2a(af0, hp, wh00.y);
                    fma2a(ag0, hp, wh01.x); fma2a(ao0, hp, wh01.y);
                    fma2a(ai1, hp, wh10.x); fma2a(af1, hp, wh10.y);
                    fma2a(ag1, hp, wh11.x); fma2a(ao1, hp, wh11.y);
                }
                float hn0, hn1;
                {
                    float gi = hadd2(ai0), gf = hadd2(af0), gg = hadd2(ag0), go = hadd2(ao0);
                    float cn = fmaf(sigm(gf), c[j0], sigm(gi) * tanhx(gg));
                    c[j0] = cn; hn0 = sigm(go) * tanhx(cn);
                }
                {
                    float gi = hadd2(ai1), gf = hadd2(af1), gg = hadd2(ag1), go = hadd2(ao1);
                    float cn = fmaf(sigm(gf), c[j1], sigm(gi) * tanhx(gg));
                    c[j1] = cn; hn1 = sigm(go) * tanhx(cn);
                }
                hnew[jj] = pack2(hn0, hn1);
            }
            {   // tail j = 16
                const int j = 16;
                u64 ai, af, ag, ao;
#pragma unroll
                for (int p = 0; p < NP; p++) {
                    ulonglong2 wi0 = sWih[(j * NP + p) * 2 + 0];
                    ulonglong2 wi1 = sWih[(j * NP + p) * 2 + 1];
                    ulonglong2 wh0 = CWH(j, p, 0);
                    ulonglong2 wh1 = CWH(j, p, 1);
                    u64 xp = xi[p], hp = h[p];
                    if (p == 0) {
                        ai = mul2(xp, wi0.x); af = mul2(xp, wi0.y);
                        ag = mul2(xp, wi1.x); ao = mul2(xp, wi1.y);
                    } else {
                        fma2a(ai, xp, wi0.x); fma2a(af, xp, wi0.y);
                        fma2a(ag, xp, wi1.x); fma2a(ao, xp, wi1.y);
                    }
                    fma2a(ai, hp, wh0.x); fma2a(af, hp, wh0.y);
                    fma2a(ag, hp, wh1.x); fma2a(ao, hp, wh1.y);
                }
                float gi = hadd2(ai), gf = hadd2(af), gg = hadd2(ag), go = hadd2(ao);
                float cn = fmaf(sigm(gf), c[j], sigm(gi) * tanhx(gg));
                c[j] = cn;
                hnew[8] = pack2(sigm(go) * tanhx(cn), 1.0f);
            }
        } else {
            // ---- feedback phase: gates = h@Wcomb ((i,f) LDS, (g,o) LDC) ----
#pragma unroll
            for (int jj = 0; jj < 8; jj++) {
                const int j0 = 2 * jj, j1 = 2 * jj + 1;
                u64 ai0, af0, ag0, ao0, ai1, af1, ag1, ao1;
#pragma unroll
                for (int p = 0; p < NP; p++) {
                    ulonglong2 wif0 = sWcIF[j0 * NP + p];
                    ulonglong2 wif1 = sWcIF[j1 * NP + p];
                    ulonglong2 wgo0 = CCGO(j0, p);
                    ulonglong2 wgo1 = CCGO(j1, p);
                    u64 hp = h[p];
                    if (p == 0) {
                        ai0 = mul2(hp, wif0.x); af0 = mul2(hp, wif0.y);
                        ag0 = mul2(hp, wgo0.x); ao0 = mul2(hp, wgo0.y);
                        ai1 = mul2(hp, wif1.x); af1 = mul2(hp, wif1.y);
                        ag1 = mul2(hp, wgo1.x); ao1 = mul2(hp, wgo1.y);
                    } else {
                        fma2a(ai0, hp, wif0.x); fma2a(af0, hp, wif0.y);
                        fma2a(ag0, hp, wgo0.x); fma2a(ao0, hp, wgo0.y);
                        fma2a(ai1, hp, wif1.x); fma2a(af1, hp, wif1.y);
                        fma2a(ag1, hp, wgo1.x); fma2a(ao1, hp, wgo1.y);
                    }
                }
                float hn0, hn1;
                {
                    float gi = hadd2(ai0), gf = hadd2(af0), gg = hadd2(ag0), go = hadd2(ao0);
                    float cn = fmaf(sigm(gf), c[j0], sigm(gi) * tanhx(gg));
                    c[j0] = cn; hn0 = sigm(go) * tanhx(cn);
                }
                {
                    float gi = hadd2(ai1), gf = hadd2(af1), gg = hadd2(ag1), go = hadd2(ao1);
                    float cn = fmaf(sigm(gf), c[j1], sigm(gi) * tanhx(gg));
                    c[j1] = cn; hn1 = sigm(go) * tanhx(cn);
                }
                hnew[jj] = pack2(hn0, hn1);
            }
            {   // tail j = 16
                const int j = 16;
                u64 ai, af, ag, ao;
#pragma unroll
                for (int p = 0; p < NP; p++) {
                    ulonglong2 wif = sWcIF[j * NP + p];
                    ulonglong2 wgo = CCGO(j, p);
                    u64 hp = h[p];
                    if (p == 0) {
                        ai = mul2(hp, wif.x); af = mul2(hp, wif.y);
                        ag = mul2(hp, wgo.x); ao = mul2(hp, wgo.y);
                    } else {
                        fma2a(ai, hp, wif.x); fma2a(af, hp, wif.y);
                        fma2a(ag, hp, wgo.x); fma2a(ao, hp, wgo.y);
                    }
                }
                float gi = hadd2(ai), gf = hadd2(af), gg = hadd2(ag), go = hadd2(ao);
                float cn = fmaf(sigm(gf), c[j], sigm(gi) * tanhx(gg));
                c[j] = cn;
                hnew[8] = pack2(sigm(go) * tanhx(cn), 1.0f);
            }
        }
#pragma unroll
        for (int p = 0; p < NP; p++) h[p] = hnew[p];

        if (t >= SLBC) {
            // output GEMV (leaf: next step's gates depend only on h)
            float o[2 * NP];
#pragma unroll
            for (int ccp = 0; ccp < NP; ccp++) {
                u64 a0, a1;
#pragma unroll
                for (int p = 0; p < NP; p++) {
                    ulonglong2 w = CLIN(ccp, p);
                    if (p == 0) { a0 = mul2(h[0], w.x); a1 = mul2(h[0], w.y); }
                    else        { fma2a(a0, h[p], w.x); fma2a(a1, h[p], w.y); }
                }
                o[2 * ccp] = hadd2(a0); o[2 * ccp + 1] = hadd2(a1);
            }
            int tp = t - SLBC;
            __syncthreads();   // buffer free (prior step's STG readers done)
            u64* myRowW = (u64*)(sStage + tid * XROW);
#pragma unroll
            for (int p = 0; p < NP; p++)
                myRowW[p] = pack2(o[2 * p], (2 * p + 1 < DDIM) ? o[2 * p + 1] : 0.0f);
            __syncthreads();
#pragma unroll
            for (int k = 0; k < DDIM; k++) {
                int idx = tid + k * TPB;
                int el = idx / DDIM, d = idx % DDIM;
                og[(long)el * (TOUT * DDIM) + tp * DDIM + d] = sStage[el * XROW + d];
            }
        }
    }
}

extern "C" void kernel_launch(void* const* d_in, const int* in_sizes, int n_in,
                              void* d_out, int out_size) {
    const float* x    = (const float*)d_in[0];
    const float* Wih  = (const float*)d_in[1];
    const float* Whh  = (const float*)d_in[2];
    const float* bih  = (const float*)d_in[3];
    const float* bhh  = (const float*)d_in[4];
    const float* Wlin = (const float*)d_in[5];
    const float* blin = (const float*)d_in[6];
    const float* mih  = (const float*)d_in[7];
    const float* mhh  = (const float*)d_in[8];
    float* out = (float*)d_out;

    prep_kernel<<<1, 128>>>(Wih, Whh, bih, bhh, Wlin, blin, mih, mhh);
    void* src = nullptr;
    cudaGetSymbolAddress(&src, g_wbuf);
    cudaMemcpyToSymbolAsync(cbuf, src, CBUF_N * sizeof(ulonglong2), 0,
                            cudaMemcpyDeviceToDevice, 0);

    dim3 grid(BSZ / TPB);   // 1024 CTAs of 64 threads
    dim3 block(TPB);
    lstm_kernel<<<grid, block>>>(x, Wih, mih, bih, bhh, out);
}